// round 12
// baseline (speedup 1.0000x reference)
#include <cuda_runtime.h>
#include <math.h>
#include <stdint.h>

// Problem constants (fixed by the dataset)
#define BATCH 4
#define TSEQ  2048
#define CDIM  1024
#define NH    16
#define DH    64
#define BT    (BATCH * TSEQ)   // 8192 rows
#define BH    (BATCH * NH)     // 64 (batch*heads)

// ---------------------------------------------------------------------------
// Scratch (device globals; no allocation allowed in kernel_launch)
// ---------------------------------------------------------------------------
__device__ float g_Qh[(size_t)BH * TSEQ * DH];       // 32 MB   [bh][t][d], rope'd, *0.125
__device__ float g_Kh[(size_t)BH * TSEQ * DH];       // 32 MB   [bh][t][d], rope'd
__device__ float g_Vh[(size_t)BH * TSEQ * DH];       // 32 MB   [bh][t][d]
__device__ float g_Oh[(size_t)BT * CDIM];            // 32 MB   attention out, [b*T+t][h*64+d]
__device__ float g_cosT[TSEQ * (DH / 2)];            // rope tables
__device__ float g_sinT[TSEQ * (DH / 2)];

// ---------------------------------------------------------------------------
// Helpers
// ---------------------------------------------------------------------------
__device__ __forceinline__ uint32_t tf32u(float x) {
    uint32_t u;
    asm("cvt.rna.tf32.f32 %0, %1;" : "=r"(u) : "f"(x));
    return u;
}

#define MMA_TF32(d, a0, a1, a2, a3, b0, b1)                                  \
    asm volatile(                                                            \
        "mma.sync.aligned.m16n8k8.row.col.f32.tf32.tf32.f32 "                \
        "{%0,%1,%2,%3}, {%4,%5,%6,%7}, {%8,%9}, {%0,%1,%2,%3};"              \
        : "+f"(d[0]), "+f"(d[1]), "+f"(d[2]), "+f"(d[3])                     \
        : "r"(a0), "r"(a1), "r"(a2), "r"(a3), "r"(b0), "r"(b1))

// ---------------------------------------------------------------------------
// RoPE tables
// ---------------------------------------------------------------------------
__global__ void build_tables_kernel() {
    int idx = blockIdx.x * blockDim.x + threadIdx.x;     // t*32 + i
    if (idx >= TSEQ * (DH / 2)) return;
    int t = idx >> 5;
    int i = idx & 31;
    float theta_f = (float)pow(10000.0, -(double)(2 * i) / (double)DH);
    float angle_f = (float)t * theta_f;
    g_cosT[idx] = (float)cos((double)angle_f);
    g_sinT[idx] = (float)sin((double)angle_f);
}

// ---------------------------------------------------------------------------
// NT GEMM via tf32 mma.sync: C[M,N] = A[M,K] * B[N,K]^T, row-major.
// Block tile 256x128, BK=16, 256 threads = 8 warps (4x2), warp tile 64x64.
// Double-buffered dynamic smem, one __syncthreads per iteration.
// mode 0: plain fp32 C write.
// mode 1: QKV epilogue — each C fragment column pair (2lc, 2lc+1) is a RoPE
//         rotation pair (j, j+1); rotate in registers, scale Q by 0.125,
//         and scatter directly into g_Qh/g_Kh/g_Vh [bh][t][d].
// ---------------------------------------------------------------------------
#define GP 20   // smem row stride (uints)

__global__ __launch_bounds__(256) void gemm_nt_tf32(
    const float* __restrict__ A, const float* __restrict__ B,
    float* __restrict__ C, int M, int N, int K, int mode)
{
    extern __shared__ __align__(16) uint32_t gsm[];
    uint32_t* As = gsm;                    // [2][256*GP]
    uint32_t* Bs = gsm + 2 * 256 * GP;     // [2][128*GP]

    const int tid  = threadIdx.x;
    const int lane = tid & 31;
    const int w    = tid >> 5;
    const int lr   = lane >> 2;
    const int lc   = lane & 3;
    const int wm   = (w >> 1) * 64;        // 4 m-positions
    const int wn   = (w & 1) * 64;         // 2 n-positions
    const int bm   = blockIdx.y * 256;
    const int bn   = blockIdx.x * 128;

    // staging: A has 512 chunks (256 rows x 2 k-blocks), 2 per thread;
    //          B has 256 chunks (128 rows x 2 k-blocks), 1 per thread.
    const int ar0 = tid >> 1,        ak0 = (tid & 1) * 8;
    const int ar1 = (tid + 256) >> 1, ak1 = ((tid + 256) & 1) * 8;
    const int br_ = tid >> 1,        bk_ = (tid & 1) * 8;

    const float* Ap0 = A + (size_t)(bm + ar0) * K + ak0;
    const float* Ap1 = A + (size_t)(bm + ar1) * K + ak1;
    const float* Bp  = B + (size_t)(bn + br_) * K + bk_;
    uint32_t* AsD0 = As + ar0 * GP + ak0;
    uint32_t* AsD1 = As + ar1 * GP + ak1;
    uint32_t* BsD  = Bs + br_ * GP + bk_;
    const int ABUF = 256 * GP;             // A buffer stride
    const int BBUF = 128 * GP;             // B buffer stride

    float acc[4][8][4] = {};
    float4 a0u, a0v, a1u, a1v, bu, bv;

    // prologue: k-block 0 -> buffer 0
    a0u = *(const float4*)(Ap0);  a0v = *(const float4*)(Ap0 + 4);
    a1u = *(const float4*)(Ap1);  a1v = *(const float4*)(Ap1 + 4);
    bu  = *(const float4*)(Bp);   bv  = *(const float4*)(Bp + 4);
    *(uint4*)(AsD0)     = make_uint4(tf32u(a0u.x), tf32u(a0v.x), tf32u(a0u.y), tf32u(a0v.y));
    *(uint4*)(AsD0 + 4) = make_uint4(tf32u(a0u.z), tf32u(a0v.z), tf32u(a0u.w), tf32u(a0v.w));
    *(uint4*)(AsD1)     = make_uint4(tf32u(a1u.x), tf32u(a1v.x), tf32u(a1u.y), tf32u(a1v.y));
    *(uint4*)(AsD1 + 4) = make_uint4(tf32u(a1u.z), tf32u(a1v.z), tf32u(a1u.w), tf32u(a1v.w));
    *(uint4*)(BsD)      = make_uint4(tf32u(bu.x),  tf32u(bv.x),  tf32u(bu.y),  tf32u(bv.y));
    *(uint4*)(BsD + 4)  = make_uint4(tf32u(bu.z),  tf32u(bv.z),  tf32u(bu.w),  tf32u(bv.w));
    __syncthreads();

    const int NIT = K / 16;
    for (int it = 0; it < NIT; it++) {
        const int cur = it & 1;
        const bool more = (it + 1 < NIT);

        if (more) {
            int k0 = (it + 1) * 16;
            a0u = *(const float4*)(Ap0 + k0);  a0v = *(const float4*)(Ap0 + k0 + 4);
            a1u = *(const float4*)(Ap1 + k0);  a1v = *(const float4*)(Ap1 + k0 + 4);
            bu  = *(const float4*)(Bp + k0);   bv  = *(const float4*)(Bp + k0 + 4);
        }

        const uint32_t* Ac = As + cur * ABUF;
        const uint32_t* Bc = Bs + cur * BBUF;
#pragma unroll
        for (int kk = 0; kk < 2; kk++) {
            uint32_t a[4][4];
#pragma unroll
            for (int mt = 0; mt < 4; mt++) {
                int m = wm + mt * 16 + lr;
                uint2 p0 = *(const uint2*)&Ac[m * GP + kk * 8 + lc * 2];
                uint2 p1 = *(const uint2*)&Ac[(m + 8) * GP + kk * 8 + lc * 2];
                a[mt][0] = p0.x; a[mt][2] = p0.y;
                a[mt][1] = p1.x; a[mt][3] = p1.y;
            }
            uint32_t b[8][2];
#pragma unroll
            for (int nt = 0; nt < 8; nt++) {
                int n = wn + nt * 8 + lr;
                uint2 q = *(const uint2*)&Bc[n * GP + kk * 8 + lc * 2];
                b[nt][0] = q.x; b[nt][1] = q.y;
            }
#pragma unroll
            for (int mt = 0; mt < 4; mt++)
#pragma unroll
                for (int nt = 0; nt < 8; nt++)
                    MMA_TF32(acc[mt][nt], a[mt][0], a[mt][1], a[mt][2], a[mt][3],
                             b[nt][0], b[nt][1]);
        }

        if (more) {
            uint32_t* Ad0 = AsD0 + (cur ^ 1) * ABUF;
            uint32_t* Ad1 = AsD1 + (cur ^ 1) * ABUF;
            uint32_t* Bd  = BsD  + (cur ^ 1) * BBUF;
            *(uint4*)(Ad0)     = make_uint4(tf32u(a0u.x), tf32u(a0v.x), tf32u(a0u.y), tf32u(a0v.y));
            *(uint4*)(Ad0 + 4) = make_uint4(tf32u(a0u.z), tf32u(a0v.z), tf32u(a0u.w), tf32u(a0v.w));
            *(uint4*)(Ad1)     = make_uint4(tf32u(a1u.x), tf32u(a1v.x), tf32u(a1u.y), tf32u(a1v.y));
            *(uint4*)(Ad1 + 4) = make_uint4(tf32u(a1u.z), tf32u(a1v.z), tf32u(a1u.w), tf32u(a1v.w));
            *(uint4*)(Bd)      = make_uint4(tf32u(bu.x),  tf32u(bv.x),  tf32u(bu.y),  tf32u(bv.y));
            *(uint4*)(Bd + 4)  = make_uint4(tf32u(bu.z),  tf32u(bv.z),  tf32u(bu.w),  tf32u(bv.w));
        }
        __syncthreads();
    }

    // ---- epilogue ----
    if (mode == 0) {
#pragma unroll
        for (int mt = 0; mt < 4; mt++) {
#pragma unroll
            for (int nt = 0; nt < 8; nt++) {
                size_t r = (size_t)(bm + wm + mt * 16 + lr);
                int col = bn + wn + nt * 8 + 2 * lc;
                *(float2*)&C[r * N + col] =
                    make_float2(acc[mt][nt][0], acc[mt][nt][1]);
                *(float2*)&C[(r + 8) * N + col] =
                    make_float2(acc[mt][nt][2], acc[mt][nt][3]);
            }
        }
    } else {
        // fused RoPE + head split. col pair (2lc, 2lc+1) == rope pair (j, j+1).
#pragma unroll
        for (int mt = 0; mt < 4; mt++) {
#pragma unroll
            for (int nt = 0; nt < 8; nt++) {
                int col    = bn + wn + nt * 8 + 2 * lc;
                int s      = col >> 10;              // 0=q 1=k 2=v
                int within = col & (CDIM - 1);
                int hh     = within >> 6;
                int j      = within & (DH - 1);      // even
#pragma unroll
                for (int h2 = 0; h2 < 2; h2++) {
                    int row = bm + wm + mt * 16 + lr + 8 * h2;
                    int t   = row & (TSEQ - 1);
                    int b   = row >> 11;
                    float e0 = acc[mt][nt][2 * h2];
                    float e1 = acc[mt][nt][2 * h2 + 1];
                    size_t dst = (((size_t)(b * NH + hh) * TSEQ) + t) * DH + j;
                    if (s == 2) {
                        *(float2*)(g_Vh + dst) = make_float2(e0, e1);
                    } else {
                        float c  = g_cosT[t * 32 + (j >> 1)];
                        float sn = g_sinT[t * 32 + (j >> 1)];
                        float o0 = e0 * c - e1 * sn;
                        float o1 = e1 * c + e0 * sn;
                        if (s == 0) {
                            o0 *= 0.125f; o1 *= 0.125f;   // 1/sqrt(d_head) into Q
                            *(float2*)(g_Qh + dst) = make_float2(o0, o1);
                        } else {
                            *(float2*)(g_Kh + dst) = make_float2(o0, o1);
                        }
                    }
                }
            }
        }
    }
}

#define GEMM_SMEM ((2 * 256 * GP + 2 * 128 * GP) * (int)sizeof(uint32_t))  // 61440 B

// ---------------------------------------------------------------------------
// Flash attention, tf32 mma. Q tile = 128 rows (8 warps x m16), K tile = 64.
// (unchanged from R10 for attribution)
// ---------------------------------------------------------------------------
#define APK 72   // K smem row stride (72 % 32 == 8 -> conflict-free LDS.64)
#define APV 72   // V smem row stride
#define APP 76   // P smem row stride (76 % 32 == 12 -> conflict-free LDS.32)

__global__ __launch_bounds__(256) void attn_tc_kernel() {
    extern __shared__ uint32_t sm[];
    uint32_t* Ks = sm;                  // [64 key][APK]   d kperm'd
    uint32_t* Vs = Ks + 64 * APK;       // [64 key][APV]   natural [key][d]
    uint32_t* Ps = Vs + 64 * APV;       // [128 q][APP]    natural [q][key]

    const int tid  = threadIdx.x;
    const int lane = tid & 31;
    const int w    = tid >> 5;          // warp 0..7 -> q rows w*16..w*16+15
    const int lr   = lane >> 2;
    const int lc   = lane & 3;
    const int iq   = blockIdx.x;        // q tile (128 rows)
    const int bh   = blockIdx.y;

    const float* Qg = g_Qh + ((size_t)bh * TSEQ + iq * 128) * DH;
    const float* Kg = g_Kh + (size_t)bh * TSEQ * DH;
    const float* Vg = g_Vh + (size_t)bh * TSEQ * DH;

    // Q fragments -> registers (reused for every key tile)
    uint32_t qf[8][4];
    {
        const float* q0 = Qg + (w * 16 + lr) * DH;
        const float* q1 = q0 + 8 * DH;
#pragma unroll
        for (int kk = 0; kk < 8; kk++) {
            qf[kk][0] = tf32u(q0[kk * 8 + lc]);
            qf[kk][1] = tf32u(q1[kk * 8 + lc]);
            qf[kk][2] = tf32u(q0[kk * 8 + lc + 4]);
            qf[kk][3] = tf32u(q1[kk * 8 + lc + 4]);
        }
    }

    float oacc[8][4] = {};
    float mrow[2] = {-INFINITY, -INFINITY};
    float lrow[2] = {0.f, 0.f};

    const int NJ = 2 * iq + 2;          // key tiles covering keys <= max row
    for (int j = 0; j < NJ; j++) {
        __syncthreads();                // prior tile's Ks/Vs reads complete
        const float* Kt = Kg + (size_t)(j * 64) * DH;
        const float* Vt = Vg + (size_t)(j * 64) * DH;
#pragma unroll
        for (int i = 0; i < 4; i++) {
            int chunk = tid + i * 256;           // 0..1023
            int r = chunk >> 4;
            int c = chunk & 15;
            int b = (c >> 1) << 3;
            int h = c & 1;
            const float* src = Kt + r * DH + b + 2 * h;
            float2 u  = *(const float2*)src;
            float2 v2 = *(const float2*)(src + 4);
            // kperm block [b+4h .. b+4h+3] = (k, k+4, k+1, k+5)
            *(uint4*)&Ks[r * APK + b + 4 * h] =
                make_uint4(tf32u(u.x), tf32u(v2.x), tf32u(u.y), tf32u(v2.y));
            float4 vv = *(const float4*)(Vt + r * DH + c * 4);
            *(uint4*)&Vs[r * APV + c * 4] =
                make_uint4(tf32u(vv.x), tf32u(vv.y), tf32u(vv.z), tf32u(vv.w));
        }
        __syncthreads();

        // ---- S = Q K^T  (m16 x n64, k=64) ----
        float s[8][4] = {};
#pragma unroll
        for (int kk = 0; kk < 8; kk++) {
#pragma unroll
            for (int nt = 0; nt < 8; nt++) {
                uint2 b2 = *(const uint2*)&Ks[(nt * 8 + lr) * APK + kk * 8 + 2 * lc];
                MMA_TF32(s[nt], qf[kk][0], qf[kk][1], qf[kk][2], qf[kk][3],
                         b2.x, b2.y);
            }
        }

        // ---- causal mask (only the last two tiles can be partial) ----
        if (j >= 2 * iq) {
            int rbase = iq * 128 + w * 16 + lr;
            int cbase = j * 64 + 2 * lc;
#pragma unroll
            for (int nt = 0; nt < 8; nt++) {
#pragma unroll
                for (int e = 0; e < 4; e++) {
                    int rl = rbase + (e >> 1) * 8;
                    int cl = cbase + nt * 8 + (e & 1);
                    if (cl > rl) s[nt][e] = -INFINITY;
                }
            }
        }

        // ---- online softmax (per row half) + P store ----
#pragma unroll
        for (int h = 0; h < 2; h++) {
            float mx = -INFINITY;
#pragma unroll
            for (int nt = 0; nt < 8; nt++)
                mx = fmaxf(mx, fmaxf(s[nt][2 * h], s[nt][2 * h + 1]));
            mx = fmaxf(mx, __shfl_xor_sync(0xffffffffu, mx, 1));
            mx = fmaxf(mx, __shfl_xor_sync(0xffffffffu, mx, 2));
            float mnew = fmaxf(mrow[h], mx);
            float alpha = __expf(mrow[h] - mnew);
            float rs = 0.f;
#pragma unroll
            for (int nt = 0; nt < 8; nt++) {
                float p0 = __expf(s[nt][2 * h] - mnew);
                float p1 = __expf(s[nt][2 * h + 1] - mnew);
                s[nt][2 * h] = p0;
                s[nt][2 * h + 1] = p1;
                rs += p0 + p1;
            }
            rs += __shfl_xor_sync(0xffffffffu, rs, 1);
            rs += __shfl_xor_sync(0xffffffffu, rs, 2);
            lrow[h] = lrow[h] * alpha + rs;
            mrow[h] = mnew;
#pragma unroll
            for (int nt = 0; nt < 8; nt++) {
                oacc[nt][2 * h] *= alpha;
                oacc[nt][2 * h + 1] *= alpha;
            }
            int pr = w * 16 + lr + 8 * h;
#pragma unroll
            for (int nt = 0; nt < 8; nt++) {
                *(uint2*)&Ps[pr * APP + nt * 8 + 2 * lc] =
                    make_uint2(tf32u(s[nt][2 * h]), tf32u(s[nt][2 * h + 1]));
            }
        }
        __syncwarp();   // this warp's Ps rows only

        // ---- O += P * V  (m16 x n64, k=64 keys) ----
#pragma unroll
        for (int kk = 0; kk < 8; kk++) {
            int m = w * 16 + lr;
            uint32_t a0 = Ps[m * APP + kk * 8 + lc];
            uint32_t a1 = Ps[(m + 8) * APP + kk * 8 + lc];
            uint32_t a2 = Ps[m * APP + kk * 8 + lc + 4];
            uint32_t a3 = Ps[(m + 8) * APP + kk * 8 + lc + 4];
#pragma unroll
            for (int nt = 0; nt < 8; nt++) {
                uint32_t b0 = Vs[(kk * 8 + lc) * APV + nt * 8 + lr];
                uint32_t b1 = Vs[(kk * 8 + lc + 4) * APV + nt * 8 + lr];
                MMA_TF32(oacc[nt], a0, a1, a2, a3, b0, b1);
            }
        }
    }

    // ---- epilogue: normalize, write [b*T+t][h*64+d] ----
    const int bb = bh >> 4;
    const int hh = bh & 15;
#pragma unroll
    for (int h = 0; h < 2; h++) {
        float inv = 1.f / lrow[h];
        size_t row = (size_t)bb * TSEQ + (size_t)iq * 128 + w * 16 + lr + 8 * h;
        float* dst = g_Oh + row * CDIM + hh * DH;
#pragma unroll
        for (int nt = 0; nt < 8; nt++) {
            int col = nt * 8 + 2 * lc;
            *(float2*)&dst[col] = make_float2(oacc[nt][2 * h] * inv,
                                              oacc[nt][2 * h + 1] * inv);
        }
    }
}

// ---------------------------------------------------------------------------
// Launch
// ---------------------------------------------------------------------------
extern "C" void kernel_launch(void* const* d_in, const int* in_sizes, int n_in,
                              void* d_out, int out_size)
{
    const float* x    = (const float*)d_in[0];
    const float* Wqkv = (const float*)d_in[2];
    const float* Wout = (const float*)d_in[3];
    for (int i = 0; i < n_in; i++) {
        if (in_sizes[i] == BT * CDIM)            x    = (const float*)d_in[i];
        else if (in_sizes[i] == 3 * CDIM * CDIM) Wqkv = (const float*)d_in[i];
        else if (in_sizes[i] == CDIM * CDIM)     Wout = (const float*)d_in[i];
    }
    float* out = (float*)d_out;

    void* p_oh;
    cudaGetSymbolAddress(&p_oh, g_Oh);

    const int smem_attn = (64 * APK + 64 * APV + 128 * APP) * (int)sizeof(uint32_t);
    cudaFuncSetAttribute(attn_tc_kernel,
                         cudaFuncAttributeMaxDynamicSharedMemorySize, smem_attn);
    cudaFuncSetAttribute(gemm_nt_tf32,
                         cudaFuncAttributeMaxDynamicSharedMemorySize, GEMM_SMEM);

    // 1. RoPE tables
    build_tables_kernel<<<(TSEQ * 32 + 255) / 256, 256>>>();

    // 2. QKV = x @ Wqkv^T with fused RoPE + head split (writes g_Qh/g_Kh/g_Vh)
    gemm_nt_tf32<<<dim3(3 * CDIM / 128, BT / 256), 256, GEMM_SMEM>>>(
        x, Wqkv, nullptr, BT, 3 * CDIM, CDIM, 1);

    // 3. Flash attention (causal, tf32 mma.sync, 128-row Q tiles)
    attn_tc_kernel<<<dim3(TSEQ / 128, BH), 256, smem_attn>>>();

    // 4. out = attn_out @ Wout^T
    gemm_nt_tf32<<<dim3(CDIM / 128, BT / 256), 256, GEMM_SMEM>>>(
        (const float*)p_oh, Wout, out, BT, CDIM, CDIM, 0);
}

// round 13
// speedup vs baseline: 1.2003x; 1.2003x over previous
#include <cuda_runtime.h>
#include <math.h>
#include <stdint.h>

// Problem constants (fixed by the dataset)
#define BATCH 4
#define TSEQ  2048
#define CDIM  1024
#define NH    16
#define DH    64
#define BT    (BATCH * TSEQ)   // 8192 rows
#define BH    (BATCH * NH)     // 64 (batch*heads)

// ---------------------------------------------------------------------------
// Scratch (device globals; no allocation allowed in kernel_launch)
// ---------------------------------------------------------------------------
__device__ float g_Qh[(size_t)BH * TSEQ * DH];       // [bh][t][d], rope'd, *0.125
__device__ float g_Kh[(size_t)BH * TSEQ * DH];       // [bh][t][d], rope'd
__device__ float g_Vh[(size_t)BH * TSEQ * DH];       // [bh][t][d]
__device__ float g_Oh[(size_t)BT * CDIM];            // attention out, [b*T+t][h*64+d]
__device__ float g_cosT[TSEQ * (DH / 2)];            // rope tables
__device__ float g_sinT[TSEQ * (DH / 2)];

// ---------------------------------------------------------------------------
// Helpers
// ---------------------------------------------------------------------------
__device__ __forceinline__ uint32_t tf32u(float x) {
    uint32_t u;
    asm("cvt.rna.tf32.f32 %0, %1;" : "=r"(u) : "f"(x));
    return u;
}

// load raw fp32 bits from smem, round to tf32 (same value as cvt-before-store)
__device__ __forceinline__ uint32_t ldcvt(const uint32_t* p) {
    return tf32u(__uint_as_float(*p));
}

#define MMA_TF32(d, a0, a1, a2, a3, b0, b1)                                  \
    asm volatile(                                                            \
        "mma.sync.aligned.m16n8k8.row.col.f32.tf32.tf32.f32 "                \
        "{%0,%1,%2,%3}, {%4,%5,%6,%7}, {%8,%9}, {%0,%1,%2,%3};"              \
        : "+f"(d[0]), "+f"(d[1]), "+f"(d[2]), "+f"(d[3])                     \
        : "r"(a0), "r"(a1), "r"(a2), "r"(a3), "r"(b0), "r"(b1))

#define CP_ASYNC16(dst_u32, src_ptr)                                         \
    asm volatile("cp.async.cg.shared.global [%0], [%1], 16;"                 \
                 :: "r"(dst_u32), "l"(src_ptr))
#define CP_COMMIT() asm volatile("cp.async.commit_group;")
#define CP_WAIT(n)  asm volatile("cp.async.wait_group %0;" :: "n"(n))

__device__ __forceinline__ uint32_t smem_u32(const void* p) {
    uint32_t a;
    asm("{ .reg .u64 t; cvta.to.shared.u64 t, %1; cvt.u32.u64 %0, t; }"
        : "=r"(a) : "l"(p));
    return a;
}

// ---------------------------------------------------------------------------
// RoPE tables
// ---------------------------------------------------------------------------
__global__ void build_tables_kernel() {
    int idx = blockIdx.x * blockDim.x + threadIdx.x;     // t*32 + i
    if (idx >= TSEQ * (DH / 2)) return;
    int t = idx >> 5;
    int i = idx & 31;
    float theta_f = (float)pow(10000.0, -(double)(2 * i) / (double)DH);
    float angle_f = (float)t * theta_f;
    g_cosT[idx] = (float)cos((double)angle_f);
    g_sinT[idx] = (float)sin((double)angle_f);
}

// ---------------------------------------------------------------------------
// NT GEMM via tf32 mma.sync: C[M,N] = A[M,K] * B[N,K]^T, row-major.
// CTA tile 128x128, BK=16, 256 threads = 8 warps (4x2), warp tile 32x64.
// cp.async 3-stage pipeline (raw fp32 in smem; cvt.rna at fragment load).
// __launch_bounds__(256,2) -> <=128 regs, 2 CTAs/SM target.
// MODE 0: plain fp32 C write.
// MODE 1: fused RoPE + head split epilogue (QKV).
// ---------------------------------------------------------------------------
#define GP 20            // smem row stride (uints); 80B = 16B-aligned
#define NSTAGE 3
#define STAGE_U (2 * 128 * GP)                 // A(128 rows)+B(128 rows) per stage
#define GEMM_SMEM (NSTAGE * STAGE_U * (int)sizeof(uint32_t))   // 61440 B

template <int MODE>
__global__ __launch_bounds__(256, 2) void gemm_nt_tf32(
    const float* __restrict__ A, const float* __restrict__ B,
    float* __restrict__ C, int M, int N, int K)
{
    extern __shared__ __align__(16) uint32_t gsm[];

    const int tid  = threadIdx.x;
    const int lane = tid & 31;
    const int w    = tid >> 5;
    const int lr   = lane >> 2;
    const int lc   = lane & 3;
    const int wm   = (w >> 1) * 32;        // 4 m-positions x 32
    const int wn   = (w & 1) * 64;         // 2 n-positions x 64
    const int bm   = blockIdx.y * 128;
    const int bn   = blockIdx.x * 128;

    // staging: A and B each 128 rows x 4 x 16B chunks = 512 chunks; 2/thread
    const int r0 = (tid)       >> 1, c0 = ((tid)       & 1) * 2;  // chunks c0, c0+1? no:
    // simpler: chunk id = tid + i*256, i in 0..1 ; r = id>>2, c = id&3
    const uint32_t sbase = smem_u32(gsm);

    float acc[2][8][4] = {};

    const float* Abase = A + (size_t)bm * K;
    const float* Bbase = B + (size_t)bn * K;

    // issue one stage's cp.asyncs (A then B)
    auto issue_stage = [&](int it, int stage) {
        uint32_t sA = sbase + stage * STAGE_U * 4;
        uint32_t sB = sA + 128 * GP * 4;
        int koff = it * 16;
#pragma unroll
        for (int i = 0; i < 2; i++) {
            int id = tid + i * 256;          // 0..511
            int r = id >> 2;
            int c = id & 3;
            CP_ASYNC16(sA + (r * GP + c * 4) * 4, Abase + (size_t)r * K + koff + c * 4);
            CP_ASYNC16(sB + (r * GP + c * 4) * 4, Bbase + (size_t)r * K + koff + c * 4);
        }
    };

    const int NIT = K / 16;
    // prologue: stages 0..NSTAGE-2
#pragma unroll
    for (int s = 0; s < NSTAGE - 1; s++) {
        issue_stage(s, s);
        CP_COMMIT();
    }

    for (int it = 0; it < NIT; it++) {
        CP_WAIT(NSTAGE - 2);                 // stage it%NSTAGE landed
        __syncthreads();                     // also: all warps done with it-1

        if (it + NSTAGE - 1 < NIT) {         // prefetch into buf[(it-1)%NSTAGE]
            issue_stage(it + NSTAGE - 1, (it + NSTAGE - 1) % NSTAGE);
            CP_COMMIT();
        }

        const uint32_t* Ac = gsm + (it % NSTAGE) * STAGE_U;
        const uint32_t* Bc = Ac + 128 * GP;
#pragma unroll
        for (int kk = 0; kk < 2; kk++) {
            uint32_t a[2][4];
#pragma unroll
            for (int mt = 0; mt < 2; mt++) {
                int m = wm + mt * 16 + lr;
                a[mt][0] = ldcvt(&Ac[m * GP + kk * 8 + lc]);
                a[mt][1] = ldcvt(&Ac[(m + 8) * GP + kk * 8 + lc]);
                a[mt][2] = ldcvt(&Ac[m * GP + kk * 8 + lc + 4]);
                a[mt][3] = ldcvt(&Ac[(m + 8) * GP + kk * 8 + lc + 4]);
            }
            uint32_t b[8][2];
#pragma unroll
            for (int nt = 0; nt < 8; nt++) {
                int n = wn + nt * 8 + lr;
                b[nt][0] = ldcvt(&Bc[n * GP + kk * 8 + lc]);
                b[nt][1] = ldcvt(&Bc[n * GP + kk * 8 + lc + 4]);
            }
#pragma unroll
            for (int mt = 0; mt < 2; mt++)
#pragma unroll
                for (int nt = 0; nt < 8; nt++)
                    MMA_TF32(acc[mt][nt], a[mt][0], a[mt][1], a[mt][2], a[mt][3],
                             b[nt][0], b[nt][1]);
        }
        __syncthreads();   // all warps done reading buf[it%NSTAGE] before refill
    }

    // ---- epilogue ----
    if (MODE == 0) {
#pragma unroll
        for (int mt = 0; mt < 2; mt++) {
#pragma unroll
            for (int nt = 0; nt < 8; nt++) {
                size_t r = (size_t)(bm + wm + mt * 16 + lr);
                int col = bn + wn + nt * 8 + 2 * lc;
                *(float2*)&C[r * N + col] =
                    make_float2(acc[mt][nt][0], acc[mt][nt][1]);
                *(float2*)&C[(r + 8) * N + col] =
                    make_float2(acc[mt][nt][2], acc[mt][nt][3]);
            }
        }
    } else {
        // fused RoPE + head split. col pair (2lc, 2lc+1) == rope pair (j, j+1).
#pragma unroll
        for (int mt = 0; mt < 2; mt++) {
#pragma unroll
            for (int nt = 0; nt < 8; nt++) {
                int col    = bn + wn + nt * 8 + 2 * lc;
                int s      = col >> 10;              // 0=q 1=k 2=v
                int within = col & (CDIM - 1);
                int hh     = within >> 6;
                int j      = within & (DH - 1);      // even
#pragma unroll
                for (int h2 = 0; h2 < 2; h2++) {
                    int row = bm + wm + mt * 16 + lr + 8 * h2;
                    int t   = row & (TSEQ - 1);
                    int b   = row >> 11;
                    float e0 = acc[mt][nt][2 * h2];
                    float e1 = acc[mt][nt][2 * h2 + 1];
                    size_t dst = (((size_t)(b * NH + hh) * TSEQ) + t) * DH + j;
                    if (s == 2) {
                        *(float2*)(g_Vh + dst) = make_float2(e0, e1);
                    } else {
                        float c  = g_cosT[t * 32 + (j >> 1)];
                        float sn = g_sinT[t * 32 + (j >> 1)];
                        float o0 = e0 * c - e1 * sn;
                        float o1 = e1 * c + e0 * sn;
                        if (s == 0) {
                            o0 *= 0.125f; o1 *= 0.125f;   // 1/sqrt(d_head) into Q
                            *(float2*)(g_Qh + dst) = make_float2(o0, o1);
                        } else {
                            *(float2*)(g_Kh + dst) = make_float2(o0, o1);
                        }
                    }
                }
            }
        }
    }
}

// ---------------------------------------------------------------------------
// Flash attention, tf32 mma. Q tile = 128 rows (8 warps x m16), K tile = 64.
// (unchanged from R10 for attribution)
// ---------------------------------------------------------------------------
#define APK 72   // K smem row stride (72 % 32 == 8 -> conflict-free LDS.64)
#define APV 72   // V smem row stride
#define APP 76   // P smem row stride (76 % 32 == 12 -> conflict-free LDS.32)

__global__ __launch_bounds__(256) void attn_tc_kernel() {
    extern __shared__ uint32_t sm[];
    uint32_t* Ks = sm;                  // [64 key][APK]   d kperm'd
    uint32_t* Vs = Ks + 64 * APK;       // [64 key][APV]   natural [key][d]
    uint32_t* Ps = Vs + 64 * APV;       // [128 q][APP]    natural [q][key]

    const int tid  = threadIdx.x;
    const int lane = tid & 31;
    const int w    = tid >> 5;          // warp 0..7 -> q rows w*16..w*16+15
    const int lr   = lane >> 2;
    const int lc   = lane & 3;
    const int iq   = blockIdx.x;        // q tile (128 rows)
    const int bh   = blockIdx.y;

    const float* Qg = g_Qh + ((size_t)bh * TSEQ + iq * 128) * DH;
    const float* Kg = g_Kh + (size_t)bh * TSEQ * DH;
    const float* Vg = g_Vh + (size_t)bh * TSEQ * DH;

    // Q fragments -> registers (reused for every key tile)
    uint32_t qf[8][4];
    {
        const float* q0 = Qg + (w * 16 + lr) * DH;
        const float* q1 = q0 + 8 * DH;
#pragma unroll
        for (int kk = 0; kk < 8; kk++) {
            qf[kk][0] = tf32u(q0[kk * 8 + lc]);
            qf[kk][1] = tf32u(q1[kk * 8 + lc]);
            qf[kk][2] = tf32u(q0[kk * 8 + lc + 4]);
            qf[kk][3] = tf32u(q1[kk * 8 + lc + 4]);
        }
    }

    float oacc[8][4] = {};
    float mrow[2] = {-INFINITY, -INFINITY};
    float lrow[2] = {0.f, 0.f};

    const int NJ = 2 * iq + 2;          // key tiles covering keys <= max row
    for (int j = 0; j < NJ; j++) {
        __syncthreads();                // prior tile's Ks/Vs reads complete
        const float* Kt = Kg + (size_t)(j * 64) * DH;
        const float* Vt = Vg + (size_t)(j * 64) * DH;
#pragma unroll
        for (int i = 0; i < 4; i++) {
            int chunk = tid + i * 256;           // 0..1023
            int r = chunk >> 4;
            int c = chunk & 15;
            int b = (c >> 1) << 3;
            int h = c & 1;
            const float* src = Kt + r * DH + b + 2 * h;
            float2 u  = *(const float2*)src;
            float2 v2 = *(const float2*)(src + 4);
            // kperm block [b+4h .. b+4h+3] = (k, k+4, k+1, k+5)
            *(uint4*)&Ks[r * APK + b + 4 * h] =
                make_uint4(tf32u(u.x), tf32u(v2.x), tf32u(u.y), tf32u(v2.y));
            float4 vv = *(const float4*)(Vt + r * DH + c * 4);
            *(uint4*)&Vs[r * APV + c * 4] =
                make_uint4(tf32u(vv.x), tf32u(vv.y), tf32u(vv.z), tf32u(vv.w));
        }
        __syncthreads();

        // ---- S = Q K^T  (m16 x n64, k=64) ----
        float s[8][4] = {};
#pragma unroll
        for (int kk = 0; kk < 8; kk++) {
#pragma unroll
            for (int nt = 0; nt < 8; nt++) {
                uint2 b2 = *(const uint2*)&Ks[(nt * 8 + lr) * APK + kk * 8 + 2 * lc];
                MMA_TF32(s[nt], qf[kk][0], qf[kk][1], qf[kk][2], qf[kk][3],
                         b2.x, b2.y);
            }
        }

        // ---- causal mask (only the last two tiles can be partial) ----
        if (j >= 2 * iq) {
            int rbase = iq * 128 + w * 16 + lr;
            int cbase = j * 64 + 2 * lc;
#pragma unroll
            for (int nt = 0; nt < 8; nt++) {
#pragma unroll
                for (int e = 0; e < 4; e++) {
                    int rl = rbase + (e >> 1) * 8;
                    int cl = cbase + nt * 8 + (e & 1);
                    if (cl > rl) s[nt][e] = -INFINITY;
                }
            }
        }

        // ---- online softmax (per row half) + P store ----
#pragma unroll
        for (int h = 0; h < 2; h++) {
            float mx = -INFINITY;
#pragma unroll
            for (int nt = 0; nt < 8; nt++)
                mx = fmaxf(mx, fmaxf(s[nt][2 * h], s[nt][2 * h + 1]));
            mx = fmaxf(mx, __shfl_xor_sync(0xffffffffu, mx, 1));
            mx = fmaxf(mx, __shfl_xor_sync(0xffffffffu, mx, 2));
            float mnew = fmaxf(mrow[h], mx);
            float alpha = __expf(mrow[h] - mnew);
            float rs = 0.f;
#pragma unroll
            for (int nt = 0; nt < 8; nt++) {
                float p0 = __expf(s[nt][2 * h] - mnew);
                float p1 = __expf(s[nt][2 * h + 1] - mnew);
                s[nt][2 * h] = p0;
                s[nt][2 * h + 1] = p1;
                rs += p0 + p1;
            }
            rs += __shfl_xor_sync(0xffffffffu, rs, 1);
            rs += __shfl_xor_sync(0xffffffffu, rs, 2);
            lrow[h] = lrow[h] * alpha + rs;
            mrow[h] = mnew;
#pragma unroll
            for (int nt = 0; nt < 8; nt++) {
                oacc[nt][2 * h] *= alpha;
                oacc[nt][2 * h + 1] *= alpha;
            }
            int pr = w * 16 + lr + 8 * h;
#pragma unroll
            for (int nt = 0; nt < 8; nt++) {
                *(uint2*)&Ps[pr * APP + nt * 8 + 2 * lc] =
                    make_uint2(tf32u(s[nt][2 * h]), tf32u(s[nt][2 * h + 1]));
            }
        }
        __syncwarp();   // this warp's Ps rows only

        // ---- O += P * V  (m16 x n64, k=64 keys) ----
#pragma unroll
        for (int kk = 0; kk < 8; kk++) {
            int m = w * 16 + lr;
            uint32_t a0 = Ps[m * APP + kk * 8 + lc];
            uint32_t a1 = Ps[(m + 8) * APP + kk * 8 + lc];
            uint32_t a2 = Ps[m * APP + kk * 8 + lc + 4];
            uint32_t a3 = Ps[(m + 8) * APP + kk * 8 + lc + 4];
#pragma unroll
            for (int nt = 0; nt < 8; nt++) {
                uint32_t b0 = Vs[(kk * 8 + lc) * APV + nt * 8 + lr];
                uint32_t b1 = Vs[(kk * 8 + lc + 4) * APV + nt * 8 + lr];
                MMA_TF32(oacc[nt], a0, a1, a2, a3, b0, b1);
            }
        }
    }

    // ---- epilogue: normalize, write [b*T+t][h*64+d] ----
    const int bb = bh >> 4;
    const int hh = bh & 15;
#pragma unroll
    for (int h = 0; h < 2; h++) {
        float inv = 1.f / lrow[h];
        size_t row = (size_t)bb * TSEQ + (size_t)iq * 128 + w * 16 + lr + 8 * h;
        float* dst = g_Oh + row * CDIM + hh * DH;
#pragma unroll
        for (int nt = 0; nt < 8; nt++) {
            int col = nt * 8 + 2 * lc;
            *(float2*)&dst[col] = make_float2(oacc[nt][2 * h] * inv,
                                              oacc[nt][2 * h + 1] * inv);
        }
    }
}

// ---------------------------------------------------------------------------
// Launch
// ---------------------------------------------------------------------------
extern "C" void kernel_launch(void* const* d_in, const int* in_sizes, int n_in,
                              void* d_out, int out_size)
{
    const float* x    = (const float*)d_in[0];
    const float* Wqkv = (const float*)d_in[2];
    const float* Wout = (const float*)d_in[3];
    for (int i = 0; i < n_in; i++) {
        if (in_sizes[i] == BT * CDIM)            x    = (const float*)d_in[i];
        else if (in_sizes[i] == 3 * CDIM * CDIM) Wqkv = (const float*)d_in[i];
        else if (in_sizes[i] == CDIM * CDIM)     Wout = (const float*)d_in[i];
    }
    float* out = (float*)d_out;

    void* p_oh;
    cudaGetSymbolAddress(&p_oh, g_Oh);

    const int smem_attn = (64 * APK + 64 * APV + 128 * APP) * (int)sizeof(uint32_t);
    cudaFuncSetAttribute(attn_tc_kernel,
                         cudaFuncAttributeMaxDynamicSharedMemorySize, smem_attn);
    cudaFuncSetAttribute(gemm_nt_tf32<0>,
                         cudaFuncAttributeMaxDynamicSharedMemorySize, GEMM_SMEM);
    cudaFuncSetAttribute(gemm_nt_tf32<1>,
                         cudaFuncAttributeMaxDynamicSharedMemorySize, GEMM_SMEM);

    // 1. RoPE tables
    build_tables_kernel<<<(TSEQ * 32 + 255) / 256, 256>>>();

    // 2. QKV = x @ Wqkv^T with fused RoPE + head split (writes g_Qh/g_Kh/g_Vh)
    gemm_nt_tf32<1><<<dim3(3 * CDIM / 128, BT / 128), 256, GEMM_SMEM>>>(
        x, Wqkv, nullptr, BT, 3 * CDIM, CDIM);

    // 3. Flash attention (causal, tf32 mma.sync, 128-row Q tiles)
    attn_tc_kernel<<<dim3(TSEQ / 128, BH), 256, smem_attn>>>();

    // 4. out = attn_out @ Wout^T
    gemm_nt_tf32<0><<<dim3(CDIM / 128, BT / 128), 256, GEMM_SMEM>>>(
        (const float*)p_oh, Wout, out, BT, CDIM, CDIM);
}

// round 14
// speedup vs baseline: 1.3079x; 1.0897x over previous
#include <cuda_runtime.h>
#include <math.h>
#include <stdint.h>

// Problem constants (fixed by the dataset)
#define BATCH 4
#define TSEQ  2048
#define CDIM  1024
#define NH    16
#define DH    64
#define BT    (BATCH * TSEQ)   // 8192 rows
#define BH    (BATCH * NH)     // 64 (batch*heads)

// ---------------------------------------------------------------------------
// Scratch (device globals; no allocation allowed in kernel_launch)
// ---------------------------------------------------------------------------
__device__ float g_Qh[(size_t)BH * TSEQ * DH];       // [bh][t][d], rope'd, *0.125
__device__ float g_Kh[(size_t)BH * TSEQ * DH];       // [bh][t][d], rope'd
__device__ float g_Vh[(size_t)BH * TSEQ * DH];       // [bh][t][d]
__device__ float g_Oh[(size_t)BT * CDIM];            // attention out, [b*T+t][h*64+d]
__device__ float g_cosT[TSEQ * (DH / 2)];            // rope tables
__device__ float g_sinT[TSEQ * (DH / 2)];

// ---------------------------------------------------------------------------
// Helpers
// ---------------------------------------------------------------------------
// pack two fp32 into fp16x2: lo = first arg, hi = second arg
__device__ __forceinline__ uint32_t f16x2(float lo, float hi) {
    uint32_t r;
    asm("cvt.rn.f16x2.f32 %0, %1, %2;" : "=r"(r) : "f"(hi), "f"(lo));
    return r;
}

#define MMA_F16(d, a0, a1, a2, a3, b0, b1)                                   \
    asm volatile(                                                            \
        "mma.sync.aligned.m16n8k16.row.col.f32.f16.f16.f32 "                 \
        "{%0,%1,%2,%3}, {%4,%5,%6,%7}, {%8,%9}, {%0,%1,%2,%3};"              \
        : "+f"(d[0]), "+f"(d[1]), "+f"(d[2]), "+f"(d[3])                     \
        : "r"(a0), "r"(a1), "r"(a2), "r"(a3), "r"(b0), "r"(b1))

#define CP_ASYNC16(dst_u32, src_ptr)                                         \
    asm volatile("cp.async.cg.shared.global [%0], [%1], 16;"                 \
                 :: "r"(dst_u32), "l"(src_ptr))
#define CP_COMMIT() asm volatile("cp.async.commit_group;")
#define CP_WAIT(n)  asm volatile("cp.async.wait_group %0;" :: "n"(n))

__device__ __forceinline__ uint32_t smem_u32(const void* p) {
    uint32_t a;
    asm("{ .reg .u64 t; cvta.to.shared.u64 t, %1; cvt.u32.u64 %0, t; }"
        : "=r"(a) : "l"(p));
    return a;
}

// ---------------------------------------------------------------------------
// RoPE tables
// ---------------------------------------------------------------------------
__global__ void build_tables_kernel() {
    int idx = blockIdx.x * blockDim.x + threadIdx.x;     // t*32 + i
    if (idx >= TSEQ * (DH / 2)) return;
    int t = idx >> 5;
    int i = idx & 31;
    float theta_f = (float)pow(10000.0, -(double)(2 * i) / (double)DH);
    float angle_f = (float)t * theta_f;
    g_cosT[idx] = (float)cos((double)angle_f);
    g_sinT[idx] = (float)sin((double)angle_f);
}

// ---------------------------------------------------------------------------
// NT GEMM via fp16 mma.sync (fp32 accum): C[M,N] = A[M,K] * B[N,K]^T.
// CTA tile 128x128, BK=16 (one m16n8k16 k-step), 256 threads = 8 warps (4x2),
// warp tile 32x64. cp.async 3-stage pipeline of raw fp32; cvt.rn.f16x2 at
// fragment build. __launch_bounds__(256,2) -> 2 CTAs/SM.
// MODE 0: plain fp32 C write.  MODE 1: fused RoPE + head split (QKV).
// ---------------------------------------------------------------------------
#define GP 20            // smem row stride (fp32 words); 80B, 16B-aligned
#define NSTAGE 3
#define STAGE_U (2 * 128 * GP)                 // A + B rows per stage (words)
#define GEMM_SMEM (NSTAGE * STAGE_U * (int)sizeof(uint32_t))   // 61440 B

template <int MODE>
__global__ __launch_bounds__(256, 2) void gemm_nt_f16(
    const float* __restrict__ A, const float* __restrict__ B,
    float* __restrict__ C, int M, int N, int K)
{
    extern __shared__ __align__(16) float gsm[];

    const int tid  = threadIdx.x;
    const int lane = tid & 31;
    const int w    = tid >> 5;
    const int lr   = lane >> 2;
    const int lc   = lane & 3;
    const int wm   = (w >> 1) * 32;        // 4 m-positions x 32
    const int wn   = (w & 1) * 64;         // 2 n-positions x 64
    const int bm   = blockIdx.y * 128;
    const int bn   = blockIdx.x * 128;

    const uint32_t sbase = smem_u32(gsm);

    float acc[2][8][4] = {};

    const float* Abase = A + (size_t)bm * K;
    const float* Bbase = B + (size_t)bn * K;

    auto issue_stage = [&](int it, int stage) {
        uint32_t sA = sbase + stage * STAGE_U * 4;
        uint32_t sB = sA + 128 * GP * 4;
        int koff = it * 16;
#pragma unroll
        for (int i = 0; i < 2; i++) {
            int id = tid + i * 256;          // 0..511
            int r = id >> 2;
            int c = id & 3;
            CP_ASYNC16(sA + (r * GP + c * 4) * 4, Abase + (size_t)r * K + koff + c * 4);
            CP_ASYNC16(sB + (r * GP + c * 4) * 4, Bbase + (size_t)r * K + koff + c * 4);
        }
    };

    const int NIT = K / 16;
#pragma unroll
    for (int s = 0; s < NSTAGE - 1; s++) {
        issue_stage(s, s);
        CP_COMMIT();
    }

    for (int it = 0; it < NIT; it++) {
        CP_WAIT(NSTAGE - 2);
        __syncthreads();

        if (it + NSTAGE - 1 < NIT) {
            issue_stage(it + NSTAGE - 1, (it + NSTAGE - 1) % NSTAGE);
            CP_COMMIT();
        }

        const float* Ac = gsm + (it % NSTAGE) * STAGE_U;
        const float* Bc = Ac + 128 * GP;

        uint32_t a[2][4];
#pragma unroll
        for (int mt = 0; mt < 2; mt++) {
            const float* p0 = Ac + (wm + mt * 16 + lr) * GP;
            const float* p1 = p0 + 8 * GP;
            a[mt][0] = f16x2(p0[2 * lc],     p0[2 * lc + 1]);
            a[mt][1] = f16x2(p1[2 * lc],     p1[2 * lc + 1]);
            a[mt][2] = f16x2(p0[2 * lc + 8], p0[2 * lc + 9]);
            a[mt][3] = f16x2(p1[2 * lc + 8], p1[2 * lc + 9]);
        }
        uint32_t b[8][2];
#pragma unroll
        for (int nt = 0; nt < 8; nt++) {
            const float* pn = Bc + (wn + nt * 8 + lr) * GP;
            b[nt][0] = f16x2(pn[2 * lc],     pn[2 * lc + 1]);
            b[nt][1] = f16x2(pn[2 * lc + 8], pn[2 * lc + 9]);
        }
#pragma unroll
        for (int mt = 0; mt < 2; mt++)
#pragma unroll
            for (int nt = 0; nt < 8; nt++)
                MMA_F16(acc[mt][nt], a[mt][0], a[mt][1], a[mt][2], a[mt][3],
                        b[nt][0], b[nt][1]);

        __syncthreads();
    }

    // ---- epilogue (identical structure to R13) ----
    if (MODE == 0) {
#pragma unroll
        for (int mt = 0; mt < 2; mt++) {
#pragma unroll
            for (int nt = 0; nt < 8; nt++) {
                size_t r = (size_t)(bm + wm + mt * 16 + lr);
                int col = bn + wn + nt * 8 + 2 * lc;
                *(float2*)&C[r * N + col] =
                    make_float2(acc[mt][nt][0], acc[mt][nt][1]);
                *(float2*)&C[(r + 8) * N + col] =
                    make_float2(acc[mt][nt][2], acc[mt][nt][3]);
            }
        }
    } else {
        // fused RoPE + head split. col pair (2lc, 2lc+1) == rope pair (j, j+1).
#pragma unroll
        for (int mt = 0; mt < 2; mt++) {
#pragma unroll
            for (int nt = 0; nt < 8; nt++) {
                int col    = bn + wn + nt * 8 + 2 * lc;
                int s      = col >> 10;              // 0=q 1=k 2=v
                int within = col & (CDIM - 1);
                int hh     = within >> 6;
                int j      = within & (DH - 1);      // even
#pragma unroll
                for (int h2 = 0; h2 < 2; h2++) {
                    int row = bm + wm + mt * 16 + lr + 8 * h2;
                    int t   = row & (TSEQ - 1);
                    int b_  = row >> 11;
                    float e0 = acc[mt][nt][2 * h2];
                    float e1 = acc[mt][nt][2 * h2 + 1];
                    size_t dst = (((size_t)(b_ * NH + hh) * TSEQ) + t) * DH + j;
                    if (s == 2) {
                        *(float2*)(g_Vh + dst) = make_float2(e0, e1);
                    } else {
                        float c  = g_cosT[t * 32 + (j >> 1)];
                        float sn = g_sinT[t * 32 + (j >> 1)];
                        float o0 = e0 * c - e1 * sn;
                        float o1 = e1 * c + e0 * sn;
                        if (s == 0) {
                            o0 *= 0.125f; o1 *= 0.125f;   // 1/sqrt(d_head) into Q
                            *(float2*)(g_Qh + dst) = make_float2(o0, o1);
                        } else {
                            *(float2*)(g_Kh + dst) = make_float2(o0, o1);
                        }
                    }
                }
            }
        }
    }
}

// ---------------------------------------------------------------------------
// Flash attention, fp16 mma (fp32 accum). Q tile 128 rows (8 warps x m16),
// K tile 64. Q fragments in registers. K tile fp16 [key][176B stride],
// P fp16 [q][144B stride], V raw fp32 [key][68 words] packed at frag build.
// All strides verified conflict-free for their access patterns.
// ---------------------------------------------------------------------------
#define KSTRIDE 176                  // bytes per K row (64 fp16 + pad), 16B mult
#define PSTRIDE 144                  // bytes per P row (64 fp16 + pad)
#define APV 68                       // V row stride in fp32 words (272B)
#define ATTN_SMEM (64 * KSTRIDE + 64 * APV * 4 + 128 * PSTRIDE)   // 47104 B

__global__ __launch_bounds__(256) void attn_f16_kernel() {
    extern __shared__ __align__(16) char sm[];
    char*  Ks16 = sm;                                  // fp16 K tile
    float* Vs   = (float*)(sm + 64 * KSTRIDE);         // fp32 V tile
    char*  Ps16 = sm + 64 * KSTRIDE + 64 * APV * 4;    // fp16 P tile

    const int tid  = threadIdx.x;
    const int lane = tid & 31;
    const int w    = tid >> 5;          // warp 0..7 -> q rows w*16..w*16+15
    const int lr   = lane >> 2;
    const int lc   = lane & 3;
    const int iq   = blockIdx.x;        // q tile (128 rows)
    const int bh   = blockIdx.y;

    const float* Qg = g_Qh + ((size_t)bh * TSEQ + iq * 128) * DH;
    const float* Kg = g_Kh + (size_t)bh * TSEQ * DH;
    const float* Vg = g_Vh + (size_t)bh * TSEQ * DH;

    // Q fragments (fp16 packed) in registers, reused for all key tiles.
    // kk indexes k16 steps over d=64.
    uint32_t qf[4][4];
    {
        const float* q0 = Qg + (w * 16 + lr) * DH;
        const float* q1 = q0 + 8 * DH;
#pragma unroll
        for (int kk = 0; kk < 4; kk++) {
            int k = kk * 16 + 2 * lc;
            qf[kk][0] = f16x2(q0[k],     q0[k + 1]);
            qf[kk][1] = f16x2(q1[k],     q1[k + 1]);
            qf[kk][2] = f16x2(q0[k + 8], q0[k + 9]);
            qf[kk][3] = f16x2(q1[k + 8], q1[k + 9]);
        }
    }

    float oacc[8][4] = {};
    float mrow[2] = {-INFINITY, -INFINITY};
    float lrow[2] = {0.f, 0.f};

    const int NJ = 2 * iq + 2;          // key tiles covering keys <= max row
    for (int j = 0; j < NJ; j++) {
        __syncthreads();                // prior tile's smem reads complete
        const float* Kt = Kg + (size_t)(j * 64) * DH;
        const float* Vt = Vg + (size_t)(j * 64) * DH;
        // K: 64 rows x 8 chunks (8 k's -> 16B fp16); 512 chunks, 2/thread
#pragma unroll
        for (int i = 0; i < 2; i++) {
            int id = tid + i * 256;
            int r = id >> 3;
            int c = id & 7;
            const float* src = Kt + r * DH + c * 8;
            float4 u = *(const float4*)src;
            float4 v = *(const float4*)(src + 4);
            *(uint4*)(Ks16 + r * KSTRIDE + c * 16) =
                make_uint4(f16x2(u.x, u.y), f16x2(u.z, u.w),
                           f16x2(v.x, v.y), f16x2(v.z, v.w));
        }
        // V: raw fp32, 64 rows x 16 chunks of 4 floats; 1024 chunks, 4/thread
#pragma unroll
        for (int i = 0; i < 4; i++) {
            int id = tid + i * 256;
            int r = id >> 4;
            int c = id & 15;
            *(float4*)&Vs[r * APV + c * 4] = *(const float4*)(Vt + r * DH + c * 4);
        }
        __syncthreads();

        // ---- S = Q K^T  (m16 x n64, 4 x k16) ----
        float s[8][4] = {};
#pragma unroll
        for (int kk = 0; kk < 4; kk++) {
#pragma unroll
            for (int nt = 0; nt < 8; nt++) {
                const char* kp = Ks16 + (nt * 8 + lr) * KSTRIDE + (kk * 16 + 2 * lc) * 2;
                uint32_t b0 = *(const uint32_t*)kp;
                uint32_t b1 = *(const uint32_t*)(kp + 16);
                MMA_F16(s[nt], qf[kk][0], qf[kk][1], qf[kk][2], qf[kk][3], b0, b1);
            }
        }

        // ---- causal mask (only last two tiles can be partial) ----
        if (j >= 2 * iq) {
            int rbase = iq * 128 + w * 16 + lr;
            int cbase = j * 64 + 2 * lc;
#pragma unroll
            for (int nt = 0; nt < 8; nt++) {
#pragma unroll
                for (int e = 0; e < 4; e++) {
                    int rl = rbase + (e >> 1) * 8;
                    int cl = cbase + nt * 8 + (e & 1);
                    if (cl > rl) s[nt][e] = -INFINITY;
                }
            }
        }

        // ---- online softmax (per row half) + P store (fp16) ----
#pragma unroll
        for (int h = 0; h < 2; h++) {
            float mx = -INFINITY;
#pragma unroll
            for (int nt = 0; nt < 8; nt++)
                mx = fmaxf(mx, fmaxf(s[nt][2 * h], s[nt][2 * h + 1]));
            mx = fmaxf(mx, __shfl_xor_sync(0xffffffffu, mx, 1));
            mx = fmaxf(mx, __shfl_xor_sync(0xffffffffu, mx, 2));
            float mnew = fmaxf(mrow[h], mx);
            float alpha = __expf(mrow[h] - mnew);
            float rs = 0.f;
#pragma unroll
            for (int nt = 0; nt < 8; nt++) {
                float p0 = __expf(s[nt][2 * h] - mnew);
                float p1 = __expf(s[nt][2 * h + 1] - mnew);
                s[nt][2 * h] = p0;
                s[nt][2 * h + 1] = p1;
                rs += p0 + p1;
            }
            rs += __shfl_xor_sync(0xffffffffu, rs, 1);
            rs += __shfl_xor_sync(0xffffffffu, rs, 2);
            lrow[h] = lrow[h] * alpha + rs;
            mrow[h] = mnew;
#pragma unroll
            for (int nt = 0; nt < 8; nt++) {
                oacc[nt][2 * h] *= alpha;
                oacc[nt][2 * h + 1] *= alpha;
            }
            int pr = w * 16 + lr + 8 * h;
#pragma unroll
            for (int nt = 0; nt < 8; nt++) {
                *(uint32_t*)(Ps16 + pr * PSTRIDE + (nt * 8 + 2 * lc) * 2) =
                    f16x2(s[nt][2 * h], s[nt][2 * h + 1]);
            }
        }
        __syncwarp();   // this warp's Ps rows only

        // ---- O += P * V  (m16 x n64, 4 x k16 over keys) ----
#pragma unroll
        for (int kk = 0; kk < 4; kk++) {
            int m = w * 16 + lr;
            const char* pa0 = Ps16 + m * PSTRIDE + (kk * 16 + 2 * lc) * 2;
            const char* pa1 = pa0 + 8 * PSTRIDE;
            uint32_t a0 = *(const uint32_t*)pa0;
            uint32_t a1 = *(const uint32_t*)pa1;
            uint32_t a2 = *(const uint32_t*)(pa0 + 16);
            uint32_t a3 = *(const uint32_t*)(pa1 + 16);
#pragma unroll
            for (int nt = 0; nt < 8; nt++) {
                int col = nt * 8 + lr;
                int r0 = (kk * 16 + 2 * lc) * APV + col;
                uint32_t b0 = f16x2(Vs[r0],            Vs[r0 + APV]);
                uint32_t b1 = f16x2(Vs[r0 + 8 * APV],  Vs[r0 + 9 * APV]);
                MMA_F16(oacc[nt], a0, a1, a2, a3, b0, b1);
            }
        }
    }

    // ---- epilogue: normalize, write [b*T+t][h*64+d] ----
    const int bb = bh >> 4;
    const int hh = bh & 15;
#pragma unroll
    for (int h = 0; h < 2; h++) {
        float inv = 1.f / lrow[h];
        size_t row = (size_t)bb * TSEQ + (size_t)iq * 128 + w * 16 + lr + 8 * h;
        float* dst = g_Oh + row * CDIM + hh * DH;
#pragma unroll
        for (int nt = 0; nt < 8; nt++) {
            int col = nt * 8 + 2 * lc;
            *(float2*)&dst[col] = make_float2(oacc[nt][2 * h] * inv,
                                              oacc[nt][2 * h + 1] * inv);
        }
    }
}

// ---------------------------------------------------------------------------
// Launch
// ---------------------------------------------------------------------------
extern "C" void kernel_launch(void* const* d_in, const int* in_sizes, int n_in,
                              void* d_out, int out_size)
{
    const float* x    = (const float*)d_in[0];
    const float* Wqkv = (const float*)d_in[2];
    const float* Wout = (const float*)d_in[3];
    for (int i = 0; i < n_in; i++) {
        if (in_sizes[i] == BT * CDIM)            x    = (const float*)d_in[i];
        else if (in_sizes[i] == 3 * CDIM * CDIM) Wqkv = (const float*)d_in[i];
        else if (in_sizes[i] == CDIM * CDIM)     Wout = (const float*)d_in[i];
    }
    float* out = (float*)d_out;

    void* p_oh;
    cudaGetSymbolAddress(&p_oh, g_Oh);

    cudaFuncSetAttribute(attn_f16_kernel,
                         cudaFuncAttributeMaxDynamicSharedMemorySize, ATTN_SMEM);
    cudaFuncSetAttribute(gemm_nt_f16<0>,
                         cudaFuncAttributeMaxDynamicSharedMemorySize, GEMM_SMEM);
    cudaFuncSetAttribute(gemm_nt_f16<1>,
                         cudaFuncAttributeMaxDynamicSharedMemorySize, GEMM_SMEM);

    // 1. RoPE tables
    build_tables_kernel<<<(TSEQ * 32 + 255) / 256, 256>>>();

    // 2. QKV = x @ Wqkv^T with fused RoPE + head split (writes g_Qh/g_Kh/g_Vh)
    gemm_nt_f16<1><<<dim3(3 * CDIM / 128, BT / 128), 256, GEMM_SMEM>>>(
        x, Wqkv, nullptr, BT, 3 * CDIM, CDIM);

    // 3. Flash attention (causal, fp16 mma, 128-row Q tiles)
    attn_f16_kernel<<<dim3(TSEQ / 128, BH), 256, ATTN_SMEM>>>();

    // 4. out = attn_out @ Wout^T
    gemm_nt_f16<0><<<dim3(CDIM / 128, BT / 128), 256, GEMM_SMEM>>>(
        (const float*)p_oh, Wout, out, BT, CDIM, CDIM);
}